// round 1
// baseline (speedup 1.0000x reference)
#include <cuda_runtime.h>
#include <cuda_bf16.h>
#include <math.h>

// Problem constants
#define Bz   2
#define Tz   1024
#define Cz   1024
#define Hz   16
#define Lz   8
#define Dz   64
#define HIDz 4096
#define Vz   32000
#define NTOK (Bz * Tz)          // 2048
#define EPSz 1e-5f

// ---------------------------------------------------------------------------
// Scratch (device globals; allocation inside kernel_launch is forbidden)
// ---------------------------------------------------------------------------
__device__ float g_x  [NTOK * Cz];      // residual stream
__device__ float g_h  [NTOK * Cz];      // LN output
__device__ float g_qkv[NTOK * 3 * Cz];  // qkv projections
__device__ float g_att[NTOK * Cz];      // attention output
__device__ float g_ffn[NTOK * HIDz];    // fc1 output

// ---------------------------------------------------------------------------
// Embedding: x[b*T+t, :] = tok_emb[idx[b,t], :] + pos_emb[t, :]
// ---------------------------------------------------------------------------
__global__ void embed_kernel(const int* __restrict__ idx,
                             const float* __restrict__ tok,
                             const float* __restrict__ pos,
                             float* __restrict__ x) {
    int row = blockIdx.x;              // 0..NTOK-1
    int t   = row & (Tz - 1);
    int tokid = idx[row];
    const float* te = tok + (size_t)tokid * Cz;
    const float* pe = pos + (size_t)t * Cz;
    float* xr = x + (size_t)row * Cz;
    for (int i = threadIdx.x; i < Cz; i += blockDim.x)
        xr[i] = te[i] + pe[i];
}

// ---------------------------------------------------------------------------
// LayerNorm per row (C=1024), one block per row
// ---------------------------------------------------------------------------
__global__ void ln_kernel(const float* __restrict__ x, float* __restrict__ y,
                          const float* __restrict__ g, const float* __restrict__ b) {
    int row = blockIdx.x;
    const float* xr = x + (size_t)row * Cz;
    float s = 0.f, s2 = 0.f;
    for (int i = threadIdx.x; i < Cz; i += blockDim.x) {
        float v = xr[i];
        s += v; s2 += v * v;
    }
    // block reduce (256 threads = 8 warps)
    __shared__ float sh_s[8], sh_s2[8];
    for (int off = 16; off > 0; off >>= 1) {
        s  += __shfl_down_sync(0xffffffffu, s,  off);
        s2 += __shfl_down_sync(0xffffffffu, s2, off);
    }
    int lane = threadIdx.x & 31, wid = threadIdx.x >> 5;
    if (lane == 0) { sh_s[wid] = s; sh_s2[wid] = s2; }
    __syncthreads();
    if (wid == 0) {
        s  = (lane < 8) ? sh_s[lane]  : 0.f;
        s2 = (lane < 8) ? sh_s2[lane] : 0.f;
        for (int off = 4; off > 0; off >>= 1) {
            s  += __shfl_down_sync(0xffffffffu, s,  off);
            s2 += __shfl_down_sync(0xffffffffu, s2, off);
        }
        if (lane == 0) { sh_s[0] = s; sh_s2[0] = s2; }
    }
    __syncthreads();
    float mean = sh_s[0] * (1.f / Cz);
    float var  = sh_s2[0] * (1.f / Cz) - mean * mean;
    float rstd = rsqrtf(var + EPSz);
    float* yr = y + (size_t)row * Cz;
    for (int i = threadIdx.x; i < Cz; i += blockDim.x)
        yr[i] = (xr[i] - mean) * rstd * g[i] + b[i];
}

// ---------------------------------------------------------------------------
// GEMM NN: C[M,N] = A[M,K] @ B[K,N]   (+bias, +gelu, +residual), row-major.
// BM=BN=128, BK=8, TM=TN=8, 256 threads. M,N mult of 128; K mult of 8.
// epi: bit0 = gelu
// ---------------------------------------------------------------------------
#define GBM 128
#define GBN 128
#define GBK 8
#define GTM 8
#define GTN 8

__global__ __launch_bounds__(256)
void gemm_nn(const float* __restrict__ A, const float* __restrict__ B,
             float* __restrict__ C, int M, int N, int K,
             const float* __restrict__ bias, const float* __restrict__ res,
             int epi) {
    __shared__ float As[GBK][GBM];
    __shared__ float Bs[GBK][GBN];

    int tile_n = blockIdx.x, tile_m = blockIdx.y;
    const float* Ab = A + (size_t)tile_m * GBM * K;
    const float* Bb = B + (size_t)tile_n * GBN;
    float* Cb = C + (size_t)tile_m * GBM * N + (size_t)tile_n * GBN;

    int tid  = threadIdx.x;
    int arow = tid >> 1, acol = (tid & 1) * 4;      // A tile: 128x8
    int brow = tid >> 5, bcol = (tid & 31) * 4;     // B tile: 8x128
    int tr = (tid >> 4) * GTM, tc = (tid & 15) * GTN;

    float acc[GTM][GTN];
#pragma unroll
    for (int i = 0; i < GTM; i++)
#pragma unroll
        for (int j = 0; j < GTN; j++) acc[i][j] = 0.f;

    for (int k0 = 0; k0 < K; k0 += GBK) {
        float4 a4 = *(const float4*)(Ab + (size_t)arow * K + k0 + acol);
        As[acol + 0][arow] = a4.x;
        As[acol + 1][arow] = a4.y;
        As[acol + 2][arow] = a4.z;
        As[acol + 3][arow] = a4.w;
        float4 b4 = *(const float4*)(Bb + (size_t)(k0 + brow) * N + bcol);
        *(float4*)&Bs[brow][bcol] = b4;
        __syncthreads();
#pragma unroll
        for (int k = 0; k < GBK; k++) {
            float ra[GTM], rb[GTN];
#pragma unroll
            for (int i = 0; i < GTM; i++) ra[i] = As[k][tr + i];
#pragma unroll
            for (int j = 0; j < GTN; j++) rb[j] = Bs[k][tc + j];
#pragma unroll
            for (int i = 0; i < GTM; i++)
#pragma unroll
                for (int j = 0; j < GTN; j++)
                    acc[i][j] = fmaf(ra[i], rb[j], acc[i][j]);
        }
        __syncthreads();
    }

#pragma unroll
    for (int i = 0; i < GTM; i++) {
        size_t rowoff = (size_t)(tr + i) * N;
        size_t resoff = res ? ((size_t)(tile_m * GBM + tr + i) * N + (size_t)tile_n * GBN) : 0;
#pragma unroll
        for (int j = 0; j < GTN; j++) {
            float v = acc[i][j];
            if (bias) v += bias[tile_n * GBN + tc + j];
            if (epi & 1) v = 0.5f * v * (1.f + erff(v * 0.70710678118654752f));
            if (res) v += res[resoff + tc + j];
            Cb[rowoff + tc + j] = v;
        }
    }
}

// ---------------------------------------------------------------------------
// GEMM NT: C[M,N] = A[M,K] @ Bt[N,K]^T  (logits head). Same tiling.
// ---------------------------------------------------------------------------
__global__ __launch_bounds__(256)
void gemm_nt(const float* __restrict__ A, const float* __restrict__ Bt,
             float* __restrict__ C, int M, int N, int K) {
    __shared__ float As[GBK][GBM];
    __shared__ float Bs[GBK][GBN];

    int tile_n = blockIdx.x, tile_m = blockIdx.y;
    const float* Ab  = A  + (size_t)tile_m * GBM * K;
    const float* Bb  = Bt + (size_t)tile_n * GBN * K;
    float* Cb = C + (size_t)tile_m * GBM * N + (size_t)tile_n * GBN;

    int tid  = threadIdx.x;
    int arow = tid >> 1, acol = (tid & 1) * 4;   // 128x8 tile of A
    int brow = tid >> 1, bcol = (tid & 1) * 4;   // 128(n-rows) x 8(k) tile of Bt
    int tr = (tid >> 4) * GTM, tc = (tid & 15) * GTN;

    float acc[GTM][GTN];
#pragma unroll
    for (int i = 0; i < GTM; i++)
#pragma unroll
        for (int j = 0; j < GTN; j++) acc[i][j] = 0.f;

    for (int k0 = 0; k0 < K; k0 += GBK) {
        float4 a4 = *(const float4*)(Ab + (size_t)arow * K + k0 + acol);
        As[acol + 0][arow] = a4.x;
        As[acol + 1][arow] = a4.y;
        As[acol + 2][arow] = a4.z;
        As[acol + 3][arow] = a4.w;
        float4 b4 = *(const float4*)(Bb + (size_t)brow * K + k0 + bcol);
        Bs[bcol + 0][brow] = b4.x;
        Bs[bcol + 1][brow] = b4.y;
        Bs[bcol + 2][brow] = b4.z;
        Bs[bcol + 3][brow] = b4.w;
        __syncthreads();
#pragma unroll
        for (int k = 0; k < GBK; k++) {
            float ra[GTM], rb[GTN];
#pragma unroll
            for (int i = 0; i < GTM; i++) ra[i] = As[k][tr + i];
#pragma unroll
            for (int j = 0; j < GTN; j++) rb[j] = Bs[k][tc + j];
#pragma unroll
            for (int i = 0; i < GTM; i++)
#pragma unroll
                for (int j = 0; j < GTN; j++)
                    acc[i][j] = fmaf(ra[i], rb[j], acc[i][j]);
        }
        __syncthreads();
    }
#pragma unroll
    for (int i = 0; i < GTM; i++)
#pragma unroll
        for (int j = 0; j < GTN; j++)
            Cb[(size_t)(tr + i) * N + tc + j] = acc[i][j];
}

// ---------------------------------------------------------------------------
// Flash-style attention, fp32. One block = 128 q rows of one (b,h).
// qkv layout per token row (3*C): [q(0:1024) | k(1024:2048) | v(2048:3072)],
// each segment head-major h*64+d.
// ---------------------------------------------------------------------------
__global__ __launch_bounds__(128)
void attn_kernel(const float* __restrict__ qkv, float* __restrict__ out) {
    __shared__ float Ks[64][64];
    __shared__ float Vs[64][64];

    int bh = blockIdx.y;            // 0..31
    int b = bh >> 4, h = bh & 15;
    int qb = blockIdx.x * 128;
    int tid = threadIdx.x;
    int tq = qb + tid;              // this thread's query position
    int row = b * Tz + tq;
    const float scale = 0.125f;     // 1/sqrt(64)

    float q[Dz], o[Dz];
    const float* qr = qkv + (size_t)row * (3 * Cz) + h * Dz;
#pragma unroll
    for (int d = 0; d < Dz; d++) { q[d] = qr[d] * scale; o[d] = 0.f; }
    float m = -1e30f, l = 0.f;

    int kend = qb + 128;            // tiles needed: kt < kend (causal)
    for (int kt = 0; kt < kend; kt += 64) {
        // cooperative load of K,V tile (64 rows x 64 dims), float4-coalesced
        for (int it = 0; it < 8; it++) {
            int idx4 = it * 128 + tid;          // 0..1023
            int r = idx4 >> 4;
            int c = (idx4 & 15) * 4;
            size_t base = (size_t)(b * Tz + kt + r) * (3 * Cz) + h * Dz + c;
            float4 kv4 = *(const float4*)(qkv + base + Cz);
            *(float4*)&Ks[r][c] = kv4;
            float4 vv4 = *(const float4*)(qkv + base + 2 * Cz);
            *(float4*)&Vs[r][c] = vv4;
        }
        __syncthreads();
#pragma unroll 1
        for (int j = 0; j < 64; j++) {
            if (kt + j > tq) break;             // causal
            float s = 0.f;
#pragma unroll
            for (int d = 0; d < Dz; d++) s = fmaf(q[d], Ks[j][d], s);
            float mn = fmaxf(m, s);
            float p    = __expf(s - mn);
            float corr = __expf(m - mn);
            l = l * corr + p;
#pragma unroll
            for (int d = 0; d < Dz; d++)
                o[d] = fmaf(o[d], corr, p * Vs[j][d]);
            m = mn;
        }
        __syncthreads();
    }
    float inv = 1.f / l;
    float* orow = out + (size_t)row * Cz + h * Dz;
#pragma unroll
    for (int d = 0; d < Dz; d++) orow[d] = o[d] * inv;
}

// ---------------------------------------------------------------------------
// Launch
// ---------------------------------------------------------------------------
extern "C" void kernel_launch(void* const* d_in, const int* in_sizes, int n_in,
                              void* d_out, int out_size) {
    const int*   idx     = (const int*)  d_in[0];
    const float* tok_emb = (const float*)d_in[1];
    const float* pos_emb = (const float*)d_in[2];
    const float* qkv_w   = (const float*)d_in[3];
    const float* proj_w  = (const float*)d_in[4];
    const float* proj_b  = (const float*)d_in[5];
    const float* ln1_g   = (const float*)d_in[6];
    const float* ln1_b   = (const float*)d_in[7];
    const float* ln2_g   = (const float*)d_in[8];
    const float* ln2_b   = (const float*)d_in[9];
    const float* fc1_w   = (const float*)d_in[10];
    const float* fc1_b   = (const float*)d_in[11];
    const float* fc2_w   = (const float*)d_in[12];
    const float* fc2_b   = (const float*)d_in[13];
    const float* lnf_g   = (const float*)d_in[14];
    const float* lnf_b   = (const float*)d_in[15];
    float* out = (float*)d_out;

    float *x, *h, *qkv, *att, *ffn;
    cudaGetSymbolAddress((void**)&x,   g_x);
    cudaGetSymbolAddress((void**)&h,   g_h);
    cudaGetSymbolAddress((void**)&qkv, g_qkv);
    cudaGetSymbolAddress((void**)&att, g_att);
    cudaGetSymbolAddress((void**)&ffn, g_ffn);

    embed_kernel<<<NTOK, 256>>>(idx, tok_emb, pos_emb, x);

    for (int l = 0; l < Lz; l++) {
        const float* qw  = qkv_w  + (size_t)l * Cz * 3 * Cz;
        const float* pw  = proj_w + (size_t)l * Cz * Cz;
        const float* pb  = proj_b + (size_t)l * Cz;
        const float* w1  = fc1_w  + (size_t)l * Cz * HIDz;
        const float* b1  = fc1_b  + (size_t)l * HIDz;
        const float* w2  = fc2_w  + (size_t)l * HIDz * Cz;
        const float* b2  = fc2_b  + (size_t)l * Cz;

        ln_kernel<<<NTOK, 256>>>(x, h, ln1_g + l * Cz, ln1_b + l * Cz);
        gemm_nn<<<dim3(3 * Cz / GBN, NTOK / GBM), 256>>>(h, qw, qkv,
                                                         NTOK, 3 * Cz, Cz,
                                                         nullptr, nullptr, 0);
        attn_kernel<<<dim3(Tz / 128, Bz * Hz), 128>>>(qkv, att);
        gemm_nn<<<dim3(Cz / GBN, NTOK / GBM), 256>>>(att, pw, x,
                                                     NTOK, Cz, Cz, pb, x, 0);
        ln_kernel<<<NTOK, 256>>>(x, h, ln2_g + l * Cz, ln2_b + l * Cz);
        gemm_nn<<<dim3(HIDz / GBN, NTOK / GBM), 256>>>(h, w1, ffn,
                                                       NTOK, HIDz, Cz, b1,
                                                       nullptr, 1);
        gemm_nn<<<dim3(Cz / GBN, NTOK / GBM), 256>>>(ffn, w2, x,
                                                     NTOK, Cz, HIDz, b2, x, 0);
    }

    ln_kernel<<<NTOK, 256>>>(x, h, lnf_g, lnf_b);
    gemm_nt<<<dim3(Vz / GBN, NTOK / GBM), 256>>>(h, tok_emb, out,
                                                 NTOK, Vz, Cz);
}

// round 3
// speedup vs baseline: 3.6179x; 3.6179x over previous
#include <cuda_runtime.h>
#include <cuda_bf16.h>
#include <cstdint>
#include <math.h>

// Problem constants
#define Bz   2
#define Tz   1024
#define Cz   1024
#define Hz   16
#define Lz   8
#define Dz   64
#define HIDz 4096
#define Vz   32000
#define NTOK (Bz * Tz)          // 2048
#define EPSz 1e-5f

// ---------------------------------------------------------------------------
// PTX helpers (base ISA only: ldmatrix / mma.sync / cp.async — no "a" features)
// ---------------------------------------------------------------------------
__device__ __forceinline__ uint32_t smem_u32(const void* p) {
    uint32_t a;
    asm("{ .reg .u64 t; cvta.to.shared.u64 t, %1; cvt.u32.u64 %0, t; }"
        : "=r"(a) : "l"(p));
    return a;
}
__device__ __forceinline__ void ldsm_x4(uint32_t* r, uint32_t addr) {
    asm volatile("ldmatrix.sync.aligned.m8n8.x4.shared.b16 {%0,%1,%2,%3}, [%4];"
        : "=r"(r[0]), "=r"(r[1]), "=r"(r[2]), "=r"(r[3]) : "r"(addr));
}
__device__ __forceinline__ void ldsm_x2(uint32_t* r, uint32_t addr) {
    asm volatile("ldmatrix.sync.aligned.m8n8.x2.shared.b16 {%0,%1}, [%2];"
        : "=r"(r[0]), "=r"(r[1]) : "r"(addr));
}
__device__ __forceinline__ void mma16816(float* d, const uint32_t* a, const uint32_t* b) {
    asm volatile("mma.sync.aligned.m16n8k16.row.col.f32.bf16.bf16.f32 "
        "{%0,%1,%2,%3}, {%4,%5,%6,%7}, {%8,%9}, {%0,%1,%2,%3};"
        : "+f"(d[0]), "+f"(d[1]), "+f"(d[2]), "+f"(d[3])
        : "r"(a[0]), "r"(a[1]), "r"(a[2]), "r"(a[3]), "r"(b[0]), "r"(b[1]));
}
__device__ __forceinline__ void cp16(uint32_t saddr, const void* gaddr) {
    asm volatile("cp.async.ca.shared.global [%0], [%1], 16;"
                 :: "r"(saddr), "l"(gaddr) : "memory");
}
#define CP_COMMIT() asm volatile("cp.async.commit_group;" ::: "memory")
#define CP_WAIT0()  asm volatile("cp.async.wait_group 0;" ::: "memory")

// ---------------------------------------------------------------------------
// Scratch (device globals)
// ---------------------------------------------------------------------------
__device__ float g_x  [NTOK * Cz];
__device__ float g_h  [NTOK * Cz];
__device__ float g_qkv[NTOK * 3 * Cz];
__device__ float g_att[NTOK * Cz];
__device__ float g_ffn[NTOK * HIDz];

// Pre-transposed + hi/lo-split weights (bf16), [N, K] K-major rows
__device__ __nv_bfloat16 g_qkvT_hi[Lz * 3 * Cz * Cz];
__device__ __nv_bfloat16 g_qkvT_lo[Lz * 3 * Cz * Cz];
__device__ __nv_bfloat16 g_projT_hi[Lz * Cz * Cz];
__device__ __nv_bfloat16 g_projT_lo[Lz * Cz * Cz];
__device__ __nv_bfloat16 g_fc1T_hi[Lz * HIDz * Cz];
__device__ __nv_bfloat16 g_fc1T_lo[Lz * HIDz * Cz];
__device__ __nv_bfloat16 g_fc2T_hi[Lz * Cz * HIDz];
__device__ __nv_bfloat16 g_fc2T_lo[Lz * Cz * HIDz];
__device__ __nv_bfloat16 g_tok_hi[Vz * Cz];
__device__ __nv_bfloat16 g_tok_lo[Vz * Cz];

// ---------------------------------------------------------------------------
// Weight prep: transpose [K,N] -> [N,K] and split fp32 -> bf16 hi + lo
// ---------------------------------------------------------------------------
__global__ void wtrans_kernel(const float* __restrict__ W,
                              __nv_bfloat16* __restrict__ Th,
                              __nv_bfloat16* __restrict__ Tl,
                              int K, int N) {
    __shared__ float t[32][33];
    const float* Wl = W + (size_t)blockIdx.z * K * N;
    __nv_bfloat16* Thl = Th + (size_t)blockIdx.z * K * N;
    __nv_bfloat16* Tll = Tl + (size_t)blockIdx.z * K * N;
    int n0 = blockIdx.x * 32, k0 = blockIdx.y * 32;
    int tx = threadIdx.x, ty = threadIdx.y;
#pragma unroll
    for (int j = 0; j < 32; j += 8)
        t[ty + j][tx] = Wl[(size_t)(k0 + ty + j) * N + n0 + tx];
    __syncthreads();
#pragma unroll
    for (int j = 0; j < 32; j += 8) {
        float v = t[tx][ty + j];
        __nv_bfloat16 h = __float2bfloat16(v);
        float lo = v - __bfloat162float(h);
        size_t o = (size_t)(n0 + ty + j) * K + k0 + tx;
        Thl[o] = h;
        Tll[o] = __float2bfloat16(lo);
    }
}

__global__ void wsplit_kernel(const float* __restrict__ W,
                              __nv_bfloat16* __restrict__ Th,
                              __nv_bfloat16* __restrict__ Tl, int n) {
    int i = blockIdx.x * blockDim.x + threadIdx.x;
    if (i < n) {
        float v = W[i];
        __nv_bfloat16 h = __float2bfloat16(v);
        Th[i] = h;
        Tl[i] = __float2bfloat16(v - __bfloat162float(h));
    }
}

// ---------------------------------------------------------------------------
// mma.sync bf16 GEMM: C[M,N] = A[M,K](fp32, split on the fly) @ B[N,K]^T
// (pre-split bf16 hi/lo). 3-pass: Ah*Bh + Ah*Bl + Al*Bh, fp32 accum.
// Block 128x128, warp tile 64x32 (warp grid 2m x 4n), BK=32, double buffer.
// ---------------------------------------------------------------------------
#define PITCH 80                 // bytes per SMEM row (40 halves, conflict-free)
#define AH_OFF 0
#define AL_OFF 10240
#define BH_OFF 20480
#define BL_OFF 30720
#define STG    40960             // bytes per stage
#define GSMEM  (2 * STG)         // 81920

__global__ __launch_bounds__(256)
void gemm_mma(const float* __restrict__ A,
              const __nv_bfloat16* __restrict__ Bh,
              const __nv_bfloat16* __restrict__ Bl,
              float* __restrict__ C, int M, int N, int K,
              const float* __restrict__ bias, const float* __restrict__ res,
              int gelu) {
    extern __shared__ __align__(128) char smem[];
    uint32_t sb = smem_u32(smem);
    int tid = threadIdx.x, wid = tid >> 5, lane = tid & 31;
    int m0 = blockIdx.y * 128, n0 = blockIdx.x * 128;
    int wm = wid & 1, wn = wid >> 1;

    float acc[4][4][4];
#pragma unroll
    for (int i = 0; i < 4; i++)
#pragma unroll
        for (int j = 0; j < 4; j++)
#pragma unroll
            for (int r = 0; r < 4; r++) acc[i][j][r] = 0.f;

    // per-thread load indices
    int a_row = tid >> 3, a_q = tid & 7;            // A: 4 iters of (row+=32)
    int b_row = tid >> 2, b_seg = tid & 3;          // B: 2 iters of (row+=64)
    const int NC = K >> 5;

    float4 ar[4];

#define LDG_A(c)                                                               \
    {                                                                          \
        const float* Ab = A + (size_t)m0 * K + (c) * 32;                       \
        _Pragma("unroll")                                                      \
        for (int it = 0; it < 4; it++)                                         \
            ar[it] = *(const float4*)(Ab + (size_t)(a_row + it * 32) * K + a_q * 4); \
    }

#define STS_A(buf)                                                             \
    {                                                                          \
        char* base = smem + (buf) * STG;                                       \
        _Pragma("unroll")                                                      \
        for (int it = 0; it < 4; it++) {                                       \
            float4 v = ar[it];                                                 \
            __nv_bfloat16 h0 = __float2bfloat16(v.x);                          \
            __nv_bfloat16 h1 = __float2bfloat16(v.y);                          \
            __nv_bfloat16 h2 = __float2bfloat16(v.z);                          \
            __nv_bfloat16 h3 = __float2bfloat16(v.w);                          \
            __nv_bfloat162 ph0, ph1, pl0, pl1;                                 \
            ph0.x = h0; ph0.y = h1; ph1.x = h2; ph1.y = h3;                    \
            pl0.x = __float2bfloat16(v.x - __bfloat162float(h0));              \
            pl0.y = __float2bfloat16(v.y - __bfloat162float(h1));              \
            pl1.x = __float2bfloat16(v.z - __bfloat162float(h2));              \
            pl1.y = __float2bfloat16(v.w - __bfloat162float(h3));              \
            uint32_t off = (a_row + it * 32) * PITCH + a_q * 8;                \
            uint2 uh, ul;                                                      \
            uh.x = *(uint32_t*)&ph0; uh.y = *(uint32_t*)&ph1;                  \
            ul.x = *(uint32_t*)&pl0; ul.y = *(uint32_t*)&pl1;                  \
            *(uint2*)(base + AH_OFF + off) = uh;                               \
            *(uint2*)(base + AL_OFF + off) = ul;                               \
        }                                                                      \
    }

#define CPA_B(c, buf)                                                          \
    {                                                                          \
        uint32_t sbase = sb + (buf) * STG;                                     \
        _Pragma("unroll")                                                      \
        for (int it = 0; it < 2; it++) {                                       \
            int n = b_row + it * 64;                                           \
            uint32_t soff = n * PITCH + b_seg * 16;                            \
            size_t goff = (size_t)(n0 + n) * K + (c) * 32 + b_seg * 8;         \
            cp16(sbase + BH_OFF + soff, Bh + goff);                            \
            cp16(sbase + BL_OFF + soff, Bl + goff);                            \
        }                                                                      \
        CP_COMMIT();                                                           \
    }

    // prologue: chunk 0
    LDG_A(0);
    CPA_B(0, 0);
    STS_A(0);

    for (int c = 0; c < NC; c++) {
        int buf = c & 1;
        CP_WAIT0();
        __syncthreads();
        if (c + 1 < NC) {
            LDG_A(c + 1);
            CPA_B(c + 1, (c + 1) & 1);
        }
        // ---- compute chunk c ----
        uint32_t base = sb + buf * STG;
        int r16 = lane & 15, hsel = lane >> 4;
        int r8 = lane & 7, msel = (lane >> 3) & 1;
#pragma unroll
        for (int kk = 0; kk < 32; kk += 16) {
            uint32_t ah[4][4], al[4][4], bh[4][2], bl[4][2];
#pragma unroll
            for (int mt = 0; mt < 4; mt++) {
                uint32_t ad = (uint32_t)((wm * 64 + mt * 16 + r16) * PITCH +
                                         (kk + hsel * 8) * 2);
                ldsm_x4(ah[mt], base + AH_OFF + ad);
                ldsm_x4(al[mt], base + AL_OFF + ad);
            }
#pragma unroll
            for (int nt = 0; nt < 4; nt++) {
                uint32_t bd = (uint32_t)((wn * 32 + nt * 8 + r8) * PITCH +
                                         (kk + msel * 8) * 2);
                ldsm_x2(bh[nt], base + BH_OFF + bd);
                ldsm_x2(bl[nt], base + BL_OFF + bd);
            }
#pragma unroll
            for (int mt = 0; mt < 4; mt++)
#pragma unroll
                for (int nt = 0; nt < 4; nt++) {
                    mma16816(acc[mt][nt], ah[mt], bh[nt]);
                    mma16816(acc[mt][nt], ah[mt], bl[nt]);
                    mma16816(acc[mt][nt], al[mt], bh[nt]);
                }
        }
        if (c + 1 < NC) STS_A((c + 1) & 1);
    }

    // ---- epilogue ----
    int gid = lane >> 2, qid = lane & 3;
#pragma unroll
    for (int mt = 0; mt < 4; mt++) {
#pragma unroll
        for (int nt = 0; nt < 4; nt++) {
            int n = n0 + wn * 32 + nt * 8 + 2 * qid;
            float bsum0 = bias ? bias[n] : 0.f;
            float bsum1 = bias ? bias[n + 1] : 0.f;
#pragma unroll
            for (int half = 0; half < 2; half++) {
                int m = m0 + wm * 64 + mt * 16 + gid + half * 8;
                float v0 = acc[mt][nt][half * 2 + 0] + bsum0;
                float v1 = acc[mt][nt][half * 2 + 1] + bsum1;
                if (gelu) {
                    v0 = 0.5f * v0 * (1.f + erff(v0 * 0.70710678118654752f));
                    v1 = 0.5f * v1 * (1.f + erff(v1 * 0.70710678118654752f));
                }
                if (res) {
                    const float* rr = res + (size_t)m * N + n;
                    v0 += rr[0];
                    v1 += rr[1];
                }
                float2 o;
                o.x = v0; o.y = v1;
                *(float2*)(C + (size_t)m * N + n) = o;
            }
        }
    }
#undef LDG_A
#undef STS_A
#undef CPA_B
}

// ---------------------------------------------------------------------------
// Embedding
// ---------------------------------------------------------------------------
__global__ void embed_kernel(const int* __restrict__ idx,
                             const float* __restrict__ tok,
                             const float* __restrict__ pos,
                             float* __restrict__ x) {
    int row = blockIdx.x;
    int t   = row & (Tz - 1);
    int tokid = idx[row];
    const float* te = tok + (size_t)tokid * Cz;
    const float* pe = pos + (size_t)t * Cz;
    float* xr = x + (size_t)row * Cz;
    for (int i = threadIdx.x; i < Cz; i += blockDim.x)
        xr[i] = te[i] + pe[i];
}

// ---------------------------------------------------------------------------
// LayerNorm per row
// ---------------------------------------------------------------------------
__global__ void ln_kernel(const float* __restrict__ x, float* __restrict__ y,
                          const float* __restrict__ g, const float* __restrict__ b) {
    int row = blockIdx.x;
    const float* xr = x + (size_t)row * Cz;
    float s = 0.f, s2 = 0.f;
    for (int i = threadIdx.x; i < Cz; i += blockDim.x) {
        float v = xr[i];
        s += v; s2 += v * v;
    }
    __shared__ float sh_s[8], sh_s2[8];
    for (int off = 16; off > 0; off >>= 1) {
        s  += __shfl_down_sync(0xffffffffu, s,  off);
        s2 += __shfl_down_sync(0xffffffffu, s2, off);
    }
    int lane = threadIdx.x & 31, wid = threadIdx.x >> 5;
    if (lane == 0) { sh_s[wid] = s; sh_s2[wid] = s2; }
    __syncthreads();
    if (wid == 0) {
        s  = (lane < 8) ? sh_s[lane]  : 0.f;
        s2 = (lane < 8) ? sh_s2[lane] : 0.f;
        for (int off = 4; off > 0; off >>= 1) {
            s  += __shfl_down_sync(0xffffffffu, s,  off);
            s2 += __shfl_down_sync(0xffffffffu, s2, off);
        }
        if (lane == 0) { sh_s[0] = s; sh_s2[0] = s2; }
    }
    __syncthreads();
    float mean = sh_s[0] * (1.f / Cz);
    float var  = sh_s2[0] * (1.f / Cz) - mean * mean;
    float rstd = rsqrtf(var + EPSz);
    float* yr = y + (size_t)row * Cz;
    for (int i = threadIdx.x; i < Cz; i += blockDim.x)
        yr[i] = (xr[i] - mean) * rstd * g[i] + b[i];
}

// ---------------------------------------------------------------------------
// Flash-style attention, fp32
// ---------------------------------------------------------------------------
__global__ __launch_bounds__(128)
void attn_kernel(const float* __restrict__ qkv, float* __restrict__ out) {
    __shared__ float Ks[64][64];
    __shared__ float Vs[64][64];

    int bh = blockIdx.y;
    int b = bh >> 4, h = bh & 15;
    int qb = blockIdx.x * 128;
    int tid = threadIdx.x;
    int tq = qb + tid;
    int row = b * Tz + tq;
    const float scale = 0.125f;

    float q[Dz], o[Dz];
    const float* qr = qkv + (size_t)row * (3 * Cz) + h * Dz;
#pragma unroll
    for (int d = 0; d < Dz; d++) { q[d] = qr[d] * scale; o[d] = 0.f; }
    float m = -1e30f, l = 0.f;

    int kend = qb + 128;
    for (int kt = 0; kt < kend; kt += 64) {
        for (int it = 0; it < 8; it++) {
            int idx4 = it * 128 + tid;
            int r = idx4 >> 4;
            int c = (idx4 & 15) * 4;
            size_t base = (size_t)(b * Tz + kt + r) * (3 * Cz) + h * Dz + c;
            float4 kv4 = *(const float4*)(qkv + base + Cz);
            *(float4*)&Ks[r][c] = kv4;
            float4 vv4 = *(const float4*)(qkv + base + 2 * Cz);
            *(float4*)&Vs[r][c] = vv4;
        }
        __syncthreads();
#pragma unroll 1
        for (int j = 0; j < 64; j++) {
            if (kt + j > tq) break;
            float s = 0.f;
#pragma unroll
            for (int d = 0; d < Dz; d++) s = fmaf(q[d], Ks[j][d], s);
            float mn = fmaxf(m, s);
            float p    = __expf(s - mn);
            float corr = __expf(m - mn);
            l = l * corr + p;
#pragma unroll
            for (int d = 0; d < Dz; d++)
                o[d] = fmaf(o[d], corr, p * Vs[j][d]);
            m = mn;
        }
        __syncthreads();
    }
    float inv = 1.f / l;
    float* orow = out + (size_t)row * Cz + h * Dz;
#pragma unroll
    for (int d = 0; d < Dz; d++) orow[d] = o[d] * inv;
}

// ---------------------------------------------------------------------------
// Launch
// ---------------------------------------------------------------------------
extern "C" void kernel_launch(void* const* d_in, const int* in_sizes, int n_in,
                              void* d_out, int out_size) {
    const int*   idx     = (const int*)  d_in[0];
    const float* tok_emb = (const float*)d_in[1];
    const float* pos_emb = (const float*)d_in[2];
    const float* qkv_w   = (const float*)d_in[3];
    const float* proj_w  = (const float*)d_in[4];
    const float* proj_b  = (const float*)d_in[5];
    const float* ln1_g   = (const float*)d_in[6];
    const float* ln1_b   = (const float*)d_in[7];
    const float* ln2_g   = (const float*)d_in[8];
    const float* ln2_b   = (const float*)d_in[9];
    const float* fc1_w   = (const float*)d_in[10];
    const float* fc1_b   = (const float*)d_in[11];
    const float* fc2_w   = (const float*)d_in[12];
    const float* fc2_b   = (const float*)d_in[13];
    const float* lnf_g   = (const float*)d_in[14];
    const float* lnf_b   = (const float*)d_in[15];
    float* out = (float*)d_out;

    float *x, *h, *qkv, *att, *ffn;
    cudaGetSymbolAddress((void**)&x,   g_x);
    cudaGetSymbolAddress((void**)&h,   g_h);
    cudaGetSymbolAddress((void**)&qkv, g_qkv);
    cudaGetSymbolAddress((void**)&att, g_att);
    cudaGetSymbolAddress((void**)&ffn, g_ffn);
    __nv_bfloat16 *qkvTh, *qkvTl, *projTh, *projTl, *fc1Th, *fc1Tl, *fc2Th, *fc2Tl, *tokh, *tokl;
    cudaGetSymbolAddress((void**)&qkvTh, g_qkvT_hi);
    cudaGetSymbolAddress((void**)&qkvTl, g_qkvT_lo);
    cudaGetSymbolAddress((void**)&projTh, g_projT_hi);
    cudaGetSymbolAddress((void**)&projTl, g_projT_lo);
    cudaGetSymbolAddress((void**)&fc1Th, g_fc1T_hi);
    cudaGetSymbolAddress((void**)&fc1Tl, g_fc1T_lo);
    cudaGetSymbolAddress((void**)&fc2Th, g_fc2T_hi);
    cudaGetSymbolAddress((void**)&fc2Tl, g_fc2T_lo);
    cudaGetSymbolAddress((void**)&tokh, g_tok_hi);
    cudaGetSymbolAddress((void**)&tokl, g_tok_lo);

    cudaFuncSetAttribute(gemm_mma, cudaFuncAttributeMaxDynamicSharedMemorySize, GSMEM);

    // ---- weight prep ----
    dim3 tb(32, 8);
    wtrans_kernel<<<dim3(3 * Cz / 32, Cz / 32, Lz), tb>>>(qkv_w, qkvTh, qkvTl, Cz, 3 * Cz);
    wtrans_kernel<<<dim3(Cz / 32, Cz / 32, Lz), tb>>>(proj_w, projTh, projTl, Cz, Cz);
    wtrans_kernel<<<dim3(HIDz / 32, Cz / 32, Lz), tb>>>(fc1_w, fc1Th, fc1Tl, Cz, HIDz);
    wtrans_kernel<<<dim3(Cz / 32, HIDz / 32, Lz), tb>>>(fc2_w, fc2Th, fc2Tl, HIDz, Cz);
    wsplit_kernel<<<(Vz * Cz + 255) / 256, 256>>>(tok_emb, tokh, tokl, Vz * Cz);

    embed_kernel<<<NTOK, 256>>>(idx, tok_emb, pos_emb, x);

    for (int l = 0; l < Lz; l++) {
        const __nv_bfloat16* qwh = qkvTh + (size_t)l * 3 * Cz * Cz;
        const __nv_bfloat16* qwl = qkvTl + (size_t)l * 3 * Cz * Cz;
        const __nv_bfloat16* pwh = projTh + (size_t)l * Cz * Cz;
        const __nv_bfloat16* pwl = projTl + (size_t)l * Cz * Cz;
        const __nv_bfloat16* w1h = fc1Th + (size_t)l * Cz * HIDz;
        const __nv_bfloat16* w1l = fc1Tl + (size_t)l * Cz * HIDz;
        const __nv_bfloat16* w2h = fc2Th + (size_t)l * Cz * HIDz;
        const __nv_bfloat16* w2l = fc2Tl + (size_t)l * Cz * HIDz;
        const float* pb  = proj_b + (size_t)l * Cz;
        const float* b1  = fc1_b  + (size_t)l * HIDz;
        const float* b2  = fc2_b  + (size_t)l * Cz;

        ln_kernel<<<NTOK, 256>>>(x, h, ln1_g + l * Cz, ln1_b + l * Cz);
        gemm_mma<<<dim3(3 * Cz / 128, NTOK / 128), 256, GSMEM>>>(
            h, qwh, qwl, qkv, NTOK, 3 * Cz, Cz, nullptr, nullptr, 0);
        attn_kernel<<<dim3(Tz / 128, Bz * Hz), 128>>>(qkv, att);
        gemm_mma<<<dim3(Cz / 128, NTOK / 128), 256, GSMEM>>>(
            att, pwh, pwl, x, NTOK, Cz, Cz, pb, x, 0);
        ln_kernel<<<NTOK, 256>>>(x, h, ln2_g + l * Cz, ln2_b + l * Cz);
        gemm_mma<<<dim3(HIDz / 128, NTOK / 128), 256, GSMEM>>>(
            h, w1h, w1l, ffn, NTOK, HIDz, Cz, b1, nullptr, 1);
        gemm_mma<<<dim3(Cz / 128, NTOK / 128), 256, GSMEM>>>(
            ffn, w2h, w2l, x, NTOK, Cz, HIDz, b2, x, 0);
    }

    ln_kernel<<<NTOK, 256>>>(x, h, lnf_g, lnf_b);
    gemm_mma<<<dim3(Vz / 128, NTOK / 128), 256, GSMEM>>>(
        h, tokh, tokl, out, NTOK, Vz, Cz, nullptr, nullptr, 0);
}

// round 4
// speedup vs baseline: 3.7713x; 1.0424x over previous
#include <cuda_runtime.h>
#include <cuda_bf16.h>
#include <cstdint>
#include <math.h>

// Problem constants
#define Bz   2
#define Tz   1024
#define Cz   1024
#define Hz   16
#define Lz   8
#define Dz   64
#define HIDz 4096
#define Vz   32000
#define NTOK (Bz * Tz)          // 2048
#define EPSz 1e-5f

// ---------------------------------------------------------------------------
// PTX helpers (base ISA only)
// ---------------------------------------------------------------------------
__device__ __forceinline__ uint32_t smem_u32(const void* p) {
    uint32_t a;
    asm("{ .reg .u64 t; cvta.to.shared.u64 t, %1; cvt.u32.u64 %0, t; }"
        : "=r"(a) : "l"(p));
    return a;
}
__device__ __forceinline__ void ldsm_x4(uint32_t* r, uint32_t addr) {
    asm volatile("ldmatrix.sync.aligned.m8n8.x4.shared.b16 {%0,%1,%2,%3}, [%4];"
        : "=r"(r[0]), "=r"(r[1]), "=r"(r[2]), "=r"(r[3]) : "r"(addr));
}
__device__ __forceinline__ void mma16816(float* d, const uint32_t* a, const uint32_t* b) {
    asm volatile("mma.sync.aligned.m16n8k16.row.col.f32.bf16.bf16.f32 "
        "{%0,%1,%2,%3}, {%4,%5,%6,%7}, {%8,%9}, {%0,%1,%2,%3};"
        : "+f"(d[0]), "+f"(d[1]), "+f"(d[2]), "+f"(d[3])
        : "r"(a[0]), "r"(a[1]), "r"(a[2]), "r"(a[3]), "r"(b[0]), "r"(b[1]));
}
__device__ __forceinline__ void cp16(uint32_t saddr, const void* gaddr) {
    asm volatile("cp.async.ca.shared.global [%0], [%1], 16;"
                 :: "r"(saddr), "l"(gaddr) : "memory");
}
#define CP_COMMIT() asm volatile("cp.async.commit_group;" ::: "memory")
#define CP_WAIT1()  asm volatile("cp.async.wait_group 1;" ::: "memory")
#define CP_WAIT0()  asm volatile("cp.async.wait_group 0;" ::: "memory")

// ---------------------------------------------------------------------------
// Scratch (device globals)
// ---------------------------------------------------------------------------
__device__ float g_x  [NTOK * Cz];              // residual stream (fp32)
__device__ float g_qkv[NTOK * 3 * Cz];          // qkv projections (fp32)
// pre-split activations (bf16 hi/lo)
__device__ __nv_bfloat16 g_hh [NTOK * Cz];
__device__ __nv_bfloat16 g_hl [NTOK * Cz];
__device__ __nv_bfloat16 g_atth[NTOK * Cz];
__device__ __nv_bfloat16 g_attl[NTOK * Cz];
__device__ __nv_bfloat16 g_ffnh[NTOK * HIDz];
__device__ __nv_bfloat16 g_ffnl[NTOK * HIDz];

// Pre-transposed + hi/lo-split weights (bf16), [N, K] K-major rows
__device__ __nv_bfloat16 g_qkvT_hi[Lz * 3 * Cz * Cz];
__device__ __nv_bfloat16 g_qkvT_lo[Lz * 3 * Cz * Cz];
__device__ __nv_bfloat16 g_projT_hi[Lz * Cz * Cz];
__device__ __nv_bfloat16 g_projT_lo[Lz * Cz * Cz];
__device__ __nv_bfloat16 g_fc1T_hi[Lz * HIDz * Cz];
__device__ __nv_bfloat16 g_fc1T_lo[Lz * HIDz * Cz];
__device__ __nv_bfloat16 g_fc2T_hi[Lz * Cz * HIDz];
__device__ __nv_bfloat16 g_fc2T_lo[Lz * Cz * HIDz];
__device__ __nv_bfloat16 g_tok_hi[Vz * Cz];
__device__ __nv_bfloat16 g_tok_lo[Vz * Cz];

// ---------------------------------------------------------------------------
// Weight prep: transpose [K,N] -> [N,K] and split fp32 -> bf16 hi + lo
// ---------------------------------------------------------------------------
__global__ void wtrans_kernel(const float* __restrict__ W,
                              __nv_bfloat16* __restrict__ Th,
                              __nv_bfloat16* __restrict__ Tl,
                              int K, int N) {
    __shared__ float t[32][33];
    const float* Wl = W + (size_t)blockIdx.z * K * N;
    __nv_bfloat16* Thl = Th + (size_t)blockIdx.z * K * N;
    __nv_bfloat16* Tll = Tl + (size_t)blockIdx.z * K * N;
    int n0 = blockIdx.x * 32, k0 = blockIdx.y * 32;
    int tx = threadIdx.x, ty = threadIdx.y;
#pragma unroll
    for (int j = 0; j < 32; j += 8)
        t[ty + j][tx] = Wl[(size_t)(k0 + ty + j) * N + n0 + tx];
    __syncthreads();
#pragma unroll
    for (int j = 0; j < 32; j += 8) {
        float v = t[tx][ty + j];
        __nv_bfloat16 h = __float2bfloat16(v);
        float lo = v - __bfloat162float(h);
        size_t o = (size_t)(n0 + ty + j) * K + k0 + tx;
        Thl[o] = h;
        Tll[o] = __float2bfloat16(lo);
    }
}

__global__ void wsplit_kernel(const float* __restrict__ W,
                              __nv_bfloat16* __restrict__ Th,
                              __nv_bfloat16* __restrict__ Tl, int n) {
    int i = blockIdx.x * blockDim.x + threadIdx.x;
    if (i < n) {
        float v = W[i];
        __nv_bfloat16 h = __float2bfloat16(v);
        Th[i] = h;
        Tl[i] = __float2bfloat16(v - __bfloat162float(h));
    }
}

// ---------------------------------------------------------------------------
// mma.sync bf16 GEMM. All operands pre-split bf16 [rows, K] K-major.
// C[M,N] = (Ah+Al)[M,K] @ (Bh+Bl)[N,K]^T via 3-pass: AhBh + AhBl + AlBh.
// Block 128x128, warp 64x32 (2m x 4n), BK=32, 3-stage cp.async pipeline.
// Outputs: Cf (fp32, optional), Ch/Cl (bf16 split, optional). bias/res/gelu.
// ---------------------------------------------------------------------------
#define PITCH 80                 // bytes per SMEM row (32 halves + pad)
#define AH_OFF 0
#define AL_OFF 10240
#define BH_OFF 20480
#define BL_OFF 30720
#define STG    40960             // bytes per stage
#define NSTG   3
#define GSMEM  (NSTG * STG)      // 122880

__global__ __launch_bounds__(256)
void gemm_mma(const __nv_bfloat16* __restrict__ Ah,
              const __nv_bfloat16* __restrict__ Al,
              const __nv_bfloat16* __restrict__ Bh,
              const __nv_bfloat16* __restrict__ Bl,
              float* __restrict__ Cf,
              __nv_bfloat16* __restrict__ Ch,
              __nv_bfloat16* __restrict__ Cl,
              int M, int N, int K,
              const float* __restrict__ bias, const float* __restrict__ res,
              int gelu) {
    extern __shared__ __align__(128) char smem[];
    uint32_t sb = smem_u32(smem);
    int tid = threadIdx.x, wid = tid >> 5, lane = tid & 31;
    int m0 = blockIdx.y * 128, n0 = blockIdx.x * 128;
    int wm = wid & 1, wn = wid >> 1;

    const __nv_bfloat16* Agh = Ah + (size_t)m0 * K;
    const __nv_bfloat16* Agl = Al + (size_t)m0 * K;
    const __nv_bfloat16* Bgh = Bh + (size_t)n0 * K;
    const __nv_bfloat16* Bgl = Bl + (size_t)n0 * K;

    float acc[4][4][4];
#pragma unroll
    for (int i = 0; i < 4; i++)
#pragma unroll
        for (int j = 0; j < 4; j++)
#pragma unroll
            for (int r = 0; r < 4; r++) acc[i][j][r] = 0.f;

    const int NC = K >> 5;

#define ISSUE(c)                                                               \
    {                                                                          \
        uint32_t s0 = sb + ((c) % NSTG) * STG;                                 \
        _Pragma("unroll")                                                      \
        for (int it = 0; it < 2; it++) {                                       \
            int i = it * 256 + tid;                                            \
            int row = i >> 2, seg = i & 3;                                     \
            uint32_t so = row * PITCH + seg * 16;                              \
            size_t go = (size_t)row * K + (size_t)(c) * 32 + seg * 8;          \
            cp16(s0 + AH_OFF + so, Agh + go);                                  \
            cp16(s0 + AL_OFF + so, Agl + go);                                  \
            cp16(s0 + BH_OFF + so, Bgh + go);                                  \
            cp16(s0 + BL_OFF + so, Bgl + go);                                  \
        }                                                                      \
        CP_COMMIT();                                                           \
    }

    ISSUE(0);
    ISSUE(1);

    // ldmatrix lane addressing
    int r16 = lane & 15, hsel = lane >> 4;                  // A
    int bg = lane >> 3;
    int browoff = ((bg & 2) << 2) + (lane & 7);             // B: n-row offset 0..15
    int bkoff = (bg & 1) * 8;                               // B: k offset 0/8

    for (int c = 0; c < NC; c++) {
        if (c + 1 < NC) { CP_WAIT1(); } else { CP_WAIT0(); }
        __syncthreads();
        uint32_t base = sb + (c % NSTG) * STG;
#pragma unroll
        for (int kk = 0; kk < 32; kk += 16) {
            uint32_t ah[16], al[16], bh[8], bl[8];
#pragma unroll
            for (int mt = 0; mt < 4; mt++) {
                uint32_t ad = (uint32_t)((wm * 64 + mt * 16 + r16) * PITCH +
                                         (kk + hsel * 8) * 2);
                ldsm_x4(ah + 4 * mt, base + AH_OFF + ad);
                ldsm_x4(al + 4 * mt, base + AL_OFF + ad);
            }
#pragma unroll
            for (int ntp = 0; ntp < 2; ntp++) {
                uint32_t bd = (uint32_t)((wn * 32 + ntp * 16 + browoff) * PITCH +
                                         (kk + bkoff) * 2);
                ldsm_x4(bh + 4 * ntp, base + BH_OFF + bd);
                ldsm_x4(bl + 4 * ntp, base + BL_OFF + bd);
            }
#pragma unroll
            for (int mt = 0; mt < 4; mt++)
#pragma unroll
                for (int nt = 0; nt < 4; nt++) {
                    mma16816(acc[mt][nt], ah + 4 * mt, bh + 2 * nt);
                    mma16816(acc[mt][nt], ah + 4 * mt, bl + 2 * nt);
                    mma16816(acc[mt][nt], al + 4 * mt, bh + 2 * nt);
                }
        }
        __syncthreads();
        if (c + 2 < NC) ISSUE(c + 2);
    }
#undef ISSUE

    // ---- epilogue ----
    int gid = lane >> 2, qid = lane & 3;
#pragma unroll
    for (int mt = 0; mt < 4; mt++) {
#pragma unroll
        for (int nt = 0; nt < 4; nt++) {
            int n = n0 + wn * 32 + nt * 8 + 2 * qid;
            float bsum0 = bias ? bias[n] : 0.f;
            float bsum1 = bias ? bias[n + 1] : 0.f;
#pragma unroll
            for (int half = 0; half < 2; half++) {
                int m = m0 + wm * 64 + mt * 16 + gid + half * 8;
                float v0 = acc[mt][nt][half * 2 + 0] + bsum0;
                float v1 = acc[mt][nt][half * 2 + 1] + bsum1;
                if (gelu) {
                    v0 = 0.5f * v0 * (1.f + erff(v0 * 0.70710678118654752f));
                    v1 = 0.5f * v1 * (1.f + erff(v1 * 0.70710678118654752f));
                }
                if (res) {
                    const float* rr = res + (size_t)m * N + n;
                    v0 += rr[0];
                    v1 += rr[1];
                }
                if (Cf) {
                    float2 o;
                    o.x = v0; o.y = v1;
                    *(float2*)(Cf + (size_t)m * N + n) = o;
                }
                if (Ch) {
                    __nv_bfloat162 oh, ol;
                    oh.x = __float2bfloat16(v0);
                    oh.y = __float2bfloat16(v1);
                    ol.x = __float2bfloat16(v0 - __bfloat162float(oh.x));
                    ol.y = __float2bfloat16(v1 - __bfloat162float(oh.y));
                    *(__nv_bfloat162*)(Ch + (size_t)m * N + n) = oh;
                    *(__nv_bfloat162*)(Cl + (size_t)m * N + n) = ol;
                }
            }
        }
    }
}

// ---------------------------------------------------------------------------
// Embedding
// ---------------------------------------------------------------------------
__global__ void embed_kernel(const int* __restrict__ idx,
                             const float* __restrict__ tok,
                             const float* __restrict__ pos,
                             float* __restrict__ x) {
    int row = blockIdx.x;
    int t   = row & (Tz - 1);
    int tokid = idx[row];
    const float* te = tok + (size_t)tokid * Cz;
    const float* pe = pos + (size_t)t * Cz;
    float* xr = x + (size_t)row * Cz;
    for (int i = threadIdx.x; i < Cz; i += blockDim.x)
        xr[i] = te[i] + pe[i];
}

// ---------------------------------------------------------------------------
// LayerNorm per row, writes bf16 hi/lo split
// ---------------------------------------------------------------------------
__global__ void ln_kernel(const float* __restrict__ x,
                          __nv_bfloat16* __restrict__ yh,
                          __nv_bfloat16* __restrict__ yl,
                          const float* __restrict__ g, const float* __restrict__ b) {
    int row = blockIdx.x;
    const float* xr = x + (size_t)row * Cz;
    float s = 0.f, s2 = 0.f;
    for (int i = threadIdx.x; i < Cz; i += blockDim.x) {
        float v = xr[i];
        s += v; s2 += v * v;
    }
    __shared__ float sh_s[8], sh_s2[8];
    for (int off = 16; off > 0; off >>= 1) {
        s  += __shfl_down_sync(0xffffffffu, s,  off);
        s2 += __shfl_down_sync(0xffffffffu, s2, off);
    }
    int lane = threadIdx.x & 31, wid = threadIdx.x >> 5;
    if (lane == 0) { sh_s[wid] = s; sh_s2[wid] = s2; }
    __syncthreads();
    if (wid == 0) {
        s  = (lane < 8) ? sh_s[lane]  : 0.f;
        s2 = (lane < 8) ? sh_s2[lane] : 0.f;
        for (int off = 4; off > 0; off >>= 1) {
            s  += __shfl_down_sync(0xffffffffu, s,  off);
            s2 += __shfl_down_sync(0xffffffffu, s2, off);
        }
        if (lane == 0) { sh_s[0] = s; sh_s2[0] = s2; }
    }
    __syncthreads();
    float mean = sh_s[0] * (1.f / Cz);
    float var  = sh_s2[0] * (1.f / Cz) - mean * mean;
    float rstd = rsqrtf(var + EPSz);
    __nv_bfloat16* yhr = yh + (size_t)row * Cz;
    __nv_bfloat16* ylr = yl + (size_t)row * Cz;
    for (int i = threadIdx.x; i < Cz; i += blockDim.x) {
        float v = (xr[i] - mean) * rstd * g[i] + b[i];
        __nv_bfloat16 h = __float2bfloat16(v);
        yhr[i] = h;
        ylr[i] = __float2bfloat16(v - __bfloat162float(h));
    }
}

// ---------------------------------------------------------------------------
// Flash-style attention, fp32, exp-halved; writes bf16 hi/lo split output.
// ---------------------------------------------------------------------------
__global__ __launch_bounds__(128)
void attn_kernel(const float* __restrict__ qkv,
                 __nv_bfloat16* __restrict__ oh,
                 __nv_bfloat16* __restrict__ ol) {
    __shared__ float Ks[64][64];
    __shared__ float Vs[64][64];

    int bh = blockIdx.y;
    int b = bh >> 4, h = bh & 15;
    int qb = blockIdx.x * 128;
    int tid = threadIdx.x;
    int tq = qb + tid;
    int row = b * Tz + tq;
    const float scale = 0.125f;

    float q[Dz], o[Dz];
    const float* qr = qkv + (size_t)row * (3 * Cz) + h * Dz;
#pragma unroll
    for (int d = 0; d < Dz; d++) { q[d] = qr[d] * scale; o[d] = 0.f; }
    float m = -1e30f, l = 0.f;

    int kend = qb + 128;
    for (int kt = 0; kt < kend; kt += 64) {
        for (int it = 0; it < 8; it++) {
            int idx4 = it * 128 + tid;
            int r = idx4 >> 4;
            int c = (idx4 & 15) * 4;
            size_t base = (size_t)(b * Tz + kt + r) * (3 * Cz) + h * Dz + c;
            float4 kv4 = *(const float4*)(qkv + base + Cz);
            *(float4*)&Ks[r][c] = kv4;
            float4 vv4 = *(const float4*)(qkv + base + 2 * Cz);
            *(float4*)&Vs[r][c] = vv4;
        }
        __syncthreads();
#pragma unroll 1
        for (int j = 0; j < 64; j++) {
            if (kt + j > tq) break;
            float s = 0.f;
#pragma unroll
            for (int d = 0; d < Dz; d++) s = fmaf(q[d], Ks[j][d], s);
            if (s <= m) {
                float p = __expf(s - m);
                l += p;
#pragma unroll
                for (int d = 0; d < Dz; d++)
                    o[d] = fmaf(p, Vs[j][d], o[d]);
            } else {
                // new max: p = exp(0) = 1 exactly
                float corr = __expf(m - s);
                l = fmaf(l, corr, 1.f);
#pragma unroll
                for (int d = 0; d < Dz; d++)
                    o[d] = fmaf(o[d], corr, Vs[j][d]);
                m = s;
            }
        }
        __syncthreads();
    }
    float inv = 1.f / l;
    __nv_bfloat16* ohr = oh + (size_t)row * Cz + h * Dz;
    __nv_bfloat16* olr = ol + (size_t)row * Cz + h * Dz;
#pragma unroll
    for (int d = 0; d < Dz; d += 2) {
        float v0 = o[d] * inv, v1 = o[d + 1] * inv;
        __nv_bfloat162 ph, pl;
        ph.x = __float2bfloat16(v0);
        ph.y = __float2bfloat16(v1);
        pl.x = __float2bfloat16(v0 - __bfloat162float(ph.x));
        pl.y = __float2bfloat16(v1 - __bfloat162float(ph.y));
        *(__nv_bfloat162*)(ohr + d) = ph;
        *(__nv_bfloat162*)(olr + d) = pl;
    }
}

// ---------------------------------------------------------------------------
// Launch
// ---------------------------------------------------------------------------
extern "C" void kernel_launch(void* const* d_in, const int* in_sizes, int n_in,
                              void* d_out, int out_size) {
    const int*   idx     = (const int*)  d_in[0];
    const float* tok_emb = (const float*)d_in[1];
    const float* pos_emb = (const float*)d_in[2];
    const float* qkv_w   = (const float*)d_in[3];
    const float* proj_w  = (const float*)d_in[4];
    const float* proj_b  = (const float*)d_in[5];
    const float* ln1_g   = (const float*)d_in[6];
    const float* ln1_b   = (const float*)d_in[7];
    const float* ln2_g   = (const float*)d_in[8];
    const float* ln2_b   = (const float*)d_in[9];
    const float* fc1_w   = (const float*)d_in[10];
    const float* fc1_b   = (const float*)d_in[11];
    const float* fc2_w   = (const float*)d_in[12];
    const float* fc2_b   = (const float*)d_in[13];
    const float* lnf_g   = (const float*)d_in[14];
    const float* lnf_b   = (const float*)d_in[15];
    float* out = (float*)d_out;

    float *x, *qkv;
    cudaGetSymbolAddress((void**)&x,   g_x);
    cudaGetSymbolAddress((void**)&qkv, g_qkv);
    __nv_bfloat16 *hh, *hl, *atth, *attl, *ffnh, *ffnl;
    cudaGetSymbolAddress((void**)&hh,   g_hh);
    cudaGetSymbolAddress((void**)&hl,   g_hl);
    cudaGetSymbolAddress((void**)&atth, g_atth);
    cudaGetSymbolAddress((void**)&attl, g_attl);
    cudaGetSymbolAddress((void**)&ffnh, g_ffnh);
    cudaGetSymbolAddress((void**)&ffnl, g_ffnl);
    __nv_bfloat16 *qkvTh, *qkvTl, *projTh, *projTl, *fc1Th, *fc1Tl, *fc2Th, *fc2Tl, *tokh, *tokl;
    cudaGetSymbolAddress((void**)&qkvTh, g_qkvT_hi);
    cudaGetSymbolAddress((void**)&qkvTl, g_qkvT_lo);
    cudaGetSymbolAddress((void**)&projTh, g_projT_hi);
    cudaGetSymbolAddress((void**)&projTl, g_projT_lo);
    cudaGetSymbolAddress((void**)&fc1Th, g_fc1T_hi);
    cudaGetSymbolAddress((void**)&fc1Tl, g_fc1T_lo);
    cudaGetSymbolAddress((void**)&fc2Th, g_fc2T_hi);
    cudaGetSymbolAddress((void**)&fc2Tl, g_fc2T_lo);
    cudaGetSymbolAddress((void**)&tokh, g_tok_hi);
    cudaGetSymbolAddress((void**)&tokl, g_tok_lo);

    cudaFuncSetAttribute(gemm_mma, cudaFuncAttributeMaxDynamicSharedMemorySize, GSMEM);

    // ---- weight prep ----
    dim3 tb(32, 8);
    wtrans_kernel<<<dim3(3 * Cz / 32, Cz / 32, Lz), tb>>>(qkv_w, qkvTh, qkvTl, Cz, 3 * Cz);
    wtrans_kernel<<<dim3(Cz / 32, Cz / 32, Lz), tb>>>(proj_w, projTh, projTl, Cz, Cz);
    wtrans_kernel<<<dim3(HIDz / 32, Cz / 32, Lz), tb>>>(fc1_w, fc1Th, fc1Tl, Cz, HIDz);
    wtrans_kernel<<<dim3(Cz / 32, HIDz / 32, Lz), tb>>>(fc2_w, fc2Th, fc2Tl, HIDz, Cz);
    wsplit_kernel<<<(Vz * Cz + 255) / 256, 256>>>(tok_emb, tokh, tokl, Vz * Cz);

    embed_kernel<<<NTOK, 256>>>(idx, tok_emb, pos_emb, x);

    for (int l = 0; l < Lz; l++) {
        const __nv_bfloat16* qwh = qkvTh + (size_t)l * 3 * Cz * Cz;
        const __nv_bfloat16* qwl = qkvTl + (size_t)l * 3 * Cz * Cz;
        const __nv_bfloat16* pwh = projTh + (size_t)l * Cz * Cz;
        const __nv_bfloat16* pwl = projTl + (size_t)l * Cz * Cz;
        const __nv_bfloat16* w1h = fc1Th + (size_t)l * Cz * HIDz;
        const __nv_bfloat16* w1l = fc1Tl + (size_t)l * Cz * HIDz;
        const __nv_bfloat16* w2h = fc2Th + (size_t)l * Cz * HIDz;
        const __nv_bfloat16* w2l = fc2Tl + (size_t)l * Cz * HIDz;
        const float* pb  = proj_b + (size_t)l * Cz;
        const float* b1  = fc1_b  + (size_t)l * HIDz;
        const float* b2  = fc2_b  + (size_t)l * Cz;

        ln_kernel<<<NTOK, 256>>>(x, hh, hl, ln1_g + l * Cz, ln1_b + l * Cz);
        gemm_mma<<<dim3(3 * Cz / 128, NTOK / 128), 256, GSMEM>>>(
            hh, hl, qwh, qwl, qkv, nullptr, nullptr,
            NTOK, 3 * Cz, Cz, nullptr, nullptr, 0);
        attn_kernel<<<dim3(Tz / 128, Bz * Hz), 128>>>(qkv, atth, attl);
        gemm_mma<<<dim3(Cz / 128, NTOK / 128), 256, GSMEM>>>(
            atth, attl, pwh, pwl, x, nullptr, nullptr,
            NTOK, Cz, Cz, pb, x, 0);
        ln_kernel<<<NTOK, 256>>>(x, hh, hl, ln2_g + l * Cz, ln2_b + l * Cz);
        gemm_mma<<<dim3(HIDz / 128, NTOK / 128), 256, GSMEM>>>(
            hh, hl, w1h, w1l, nullptr, ffnh, ffnl,
            NTOK, HIDz, Cz, b1, nullptr, 1);
        gemm_mma<<<dim3(Cz / 128, NTOK / 128), 256, GSMEM>>>(
            ffnh, ffnl, w2h, w2l, x, nullptr, nullptr,
            NTOK, Cz, HIDz, b2, x, 0);
    }

    ln_kernel<<<NTOK, 256>>>(x, hh, hl, lnf_g, lnf_b);
    gemm_mma<<<dim3(Vz / 128, NTOK / 128), 256, GSMEM>>>(
        hh, hl, tokh, tokl, out, nullptr, nullptr,
        NTOK, Vz, Cz, nullptr, nullptr, 0);
}

// round 5
// speedup vs baseline: 5.2184x; 1.3837x over previous
#include <cuda_runtime.h>
#include <cuda_bf16.h>
#include <cstdint>
#include <math.h>

// Problem constants
#define Bz   2
#define Tz   1024
#define Cz   1024
#define Hz   16
#define Lz   8
#define Dz   64
#define HIDz 4096
#define Vz   32000
#define NTOK (Bz * Tz)          // 2048
#define EPSz 1e-5f

// ---------------------------------------------------------------------------
// PTX helpers (base ISA only)
// ---------------------------------------------------------------------------
__device__ __forceinline__ uint32_t smem_u32(const void* p) {
    uint32_t a;
    asm("{ .reg .u64 t; cvta.to.shared.u64 t, %1; cvt.u32.u64 %0, t; }"
        : "=r"(a) : "l"(p));
    return a;
}
__device__ __forceinline__ void ldsm_x4(uint32_t* r, uint32_t addr) {
    asm volatile("ldmatrix.sync.aligned.m8n8.x4.shared.b16 {%0,%1,%2,%3}, [%4];"
        : "=r"(r[0]), "=r"(r[1]), "=r"(r[2]), "=r"(r[3]) : "r"(addr));
}
__device__ __forceinline__ void ldsm_x4t(uint32_t* r, uint32_t addr) {
    asm volatile("ldmatrix.sync.aligned.m8n8.x4.trans.shared.b16 {%0,%1,%2,%3}, [%4];"
        : "=r"(r[0]), "=r"(r[1]), "=r"(r[2]), "=r"(r[3]) : "r"(addr));
}
__device__ __forceinline__ void mma16816(float* d, const uint32_t* a, const uint32_t* b) {
    asm volatile("mma.sync.aligned.m16n8k16.row.col.f32.bf16.bf16.f32 "
        "{%0,%1,%2,%3}, {%4,%5,%6,%7}, {%8,%9}, {%0,%1,%2,%3};"
        : "+f"(d[0]), "+f"(d[1]), "+f"(d[2]), "+f"(d[3])
        : "r"(a[0]), "r"(a[1]), "r"(a[2]), "r"(a[3]), "r"(b[0]), "r"(b[1]));
}
__device__ __forceinline__ void cp16(uint32_t saddr, const void* gaddr) {
    asm volatile("cp.async.ca.shared.global [%0], [%1], 16;"
                 :: "r"(saddr), "l"(gaddr) : "memory");
}
#define CP_COMMIT() asm volatile("cp.async.commit_group;" ::: "memory")
#define CP_WAIT1()  asm volatile("cp.async.wait_group 1;" ::: "memory")
#define CP_WAIT0()  asm volatile("cp.async.wait_group 0;" ::: "memory")

__device__ __forceinline__ uint32_t packbf(float x, float y) {
    __nv_bfloat162 t;
    t.x = __float2bfloat16(x);
    t.y = __float2bfloat16(y);
    return *(uint32_t*)&t;
}

// ---------------------------------------------------------------------------
// Scratch (device globals)
// ---------------------------------------------------------------------------
__device__ float g_x[NTOK * Cz];                    // residual stream (fp32)
__device__ __nv_bfloat16 g_hh  [NTOK * Cz];
__device__ __nv_bfloat16 g_hl  [NTOK * Cz];
__device__ __nv_bfloat16 g_qkvh[NTOK * 3 * Cz];     // qkv (bf16 hi/lo)
__device__ __nv_bfloat16 g_qkvl[NTOK * 3 * Cz];
__device__ __nv_bfloat16 g_atth[NTOK * Cz];
__device__ __nv_bfloat16 g_attl[NTOK * Cz];
__device__ __nv_bfloat16 g_ffnh[NTOK * HIDz];
__device__ __nv_bfloat16 g_ffnl[NTOK * HIDz];

// Pre-transposed + hi/lo-split weights (bf16), [N, K] K-major rows
__device__ __nv_bfloat16 g_qkvT_hi[Lz * 3 * Cz * Cz];
__device__ __nv_bfloat16 g_qkvT_lo[Lz * 3 * Cz * Cz];
__device__ __nv_bfloat16 g_projT_hi[Lz * Cz * Cz];
__device__ __nv_bfloat16 g_projT_lo[Lz * Cz * Cz];
__device__ __nv_bfloat16 g_fc1T_hi[Lz * HIDz * Cz];
__device__ __nv_bfloat16 g_fc1T_lo[Lz * HIDz * Cz];
__device__ __nv_bfloat16 g_fc2T_hi[Lz * Cz * HIDz];
__device__ __nv_bfloat16 g_fc2T_lo[Lz * Cz * HIDz];
__device__ __nv_bfloat16 g_tok_hi[Vz * Cz];
__device__ __nv_bfloat16 g_tok_lo[Vz * Cz];

// ---------------------------------------------------------------------------
// Weight prep
// ---------------------------------------------------------------------------
__global__ void wtrans_kernel(const float* __restrict__ W,
                              __nv_bfloat16* __restrict__ Th,
                              __nv_bfloat16* __restrict__ Tl,
                              int K, int N) {
    __shared__ float t[32][33];
    const float* Wl = W + (size_t)blockIdx.z * K * N;
    __nv_bfloat16* Thl = Th + (size_t)blockIdx.z * K * N;
    __nv_bfloat16* Tll = Tl + (size_t)blockIdx.z * K * N;
    int n0 = blockIdx.x * 32, k0 = blockIdx.y * 32;
    int tx = threadIdx.x, ty = threadIdx.y;
#pragma unroll
    for (int j = 0; j < 32; j += 8)
        t[ty + j][tx] = Wl[(size_t)(k0 + ty + j) * N + n0 + tx];
    __syncthreads();
#pragma unroll
    for (int j = 0; j < 32; j += 8) {
        float v = t[tx][ty + j];
        __nv_bfloat16 h = __float2bfloat16(v);
        float lo = v - __bfloat162float(h);
        size_t o = (size_t)(n0 + ty + j) * K + k0 + tx;
        Thl[o] = h;
        Tll[o] = __float2bfloat16(lo);
    }
}

__global__ void wsplit_kernel(const float* __restrict__ W,
                              __nv_bfloat16* __restrict__ Th,
                              __nv_bfloat16* __restrict__ Tl, int n) {
    int i = blockIdx.x * blockDim.x + threadIdx.x;
    if (i < n) {
        float v = W[i];
        __nv_bfloat16 h = __float2bfloat16(v);
        Th[i] = h;
        Tl[i] = __float2bfloat16(v - __bfloat162float(h));
    }
}

// ---------------------------------------------------------------------------
// mma.sync bf16 GEMM (unchanged from R4)
// ---------------------------------------------------------------------------
#define PITCH 80
#define AH_OFF 0
#define AL_OFF 10240
#define BH_OFF 20480
#define BL_OFF 30720
#define STG    40960
#define NSTG   3
#define GSMEM  (NSTG * STG)

__global__ __launch_bounds__(256)
void gemm_mma(const __nv_bfloat16* __restrict__ Ah,
              const __nv_bfloat16* __restrict__ Al,
              const __nv_bfloat16* __restrict__ Bh,
              const __nv_bfloat16* __restrict__ Bl,
              float* __restrict__ Cf,
              __nv_bfloat16* __restrict__ Ch,
              __nv_bfloat16* __restrict__ Cl,
              int M, int N, int K,
              const float* __restrict__ bias, const float* __restrict__ res,
              int gelu) {
    extern __shared__ __align__(128) char smem[];
    uint32_t sb = smem_u32(smem);
    int tid = threadIdx.x, wid = tid >> 5, lane = tid & 31;
    int m0 = blockIdx.y * 128, n0 = blockIdx.x * 128;
    int wm = wid & 1, wn = wid >> 1;

    const __nv_bfloat16* Agh = Ah + (size_t)m0 * K;
    const __nv_bfloat16* Agl = Al + (size_t)m0 * K;
    const __nv_bfloat16* Bgh = Bh + (size_t)n0 * K;
    const __nv_bfloat16* Bgl = Bl + (size_t)n0 * K;

    float acc[4][4][4];
#pragma unroll
    for (int i = 0; i < 4; i++)
#pragma unroll
        for (int j = 0; j < 4; j++)
#pragma unroll
            for (int r = 0; r < 4; r++) acc[i][j][r] = 0.f;

    const int NC = K >> 5;

#define ISSUE(c)                                                               \
    {                                                                          \
        uint32_t s0 = sb + ((c) % NSTG) * STG;                                 \
        _Pragma("unroll")                                                      \
        for (int it = 0; it < 2; it++) {                                       \
            int i = it * 256 + tid;                                            \
            int row = i >> 2, seg = i & 3;                                     \
            uint32_t so = row * PITCH + seg * 16;                              \
            size_t go = (size_t)row * K + (size_t)(c) * 32 + seg * 8;          \
            cp16(s0 + AH_OFF + so, Agh + go);                                  \
            cp16(s0 + AL_OFF + so, Agl + go);                                  \
            cp16(s0 + BH_OFF + so, Bgh + go);                                  \
            cp16(s0 + BL_OFF + so, Bgl + go);                                  \
        }                                                                      \
        CP_COMMIT();                                                           \
    }

    ISSUE(0);
    ISSUE(1);

    int r16 = lane & 15, hsel = lane >> 4;
    int bg = lane >> 3;
    int browoff = ((bg & 2) << 2) + (lane & 7);
    int bkoff = (bg & 1) * 8;

    for (int c = 0; c < NC; c++) {
        if (c + 1 < NC) { CP_WAIT1(); } else { CP_WAIT0(); }
        __syncthreads();
        uint32_t base = sb + (c % NSTG) * STG;
#pragma unroll
        for (int kk = 0; kk < 32; kk += 16) {
            uint32_t ah[16], al[16], bh[8], bl[8];
#pragma unroll
            for (int mt = 0; mt < 4; mt++) {
                uint32_t ad = (uint32_t)((wm * 64 + mt * 16 + r16) * PITCH +
                                         (kk + hsel * 8) * 2);
                ldsm_x4(ah + 4 * mt, base + AH_OFF + ad);
                ldsm_x4(al + 4 * mt, base + AL_OFF + ad);
            }
#pragma unroll
            for (int ntp = 0; ntp < 2; ntp++) {
                uint32_t bd = (uint32_t)((wn * 32 + ntp * 16 + browoff) * PITCH +
                                         (kk + bkoff) * 2);
                ldsm_x4(bh + 4 * ntp, base + BH_OFF + bd);
                ldsm_x4(bl + 4 * ntp, base + BL_OFF + bd);
            }
#pragma unroll
            for (int mt = 0; mt < 4; mt++)
#pragma unroll
                for (int nt = 0; nt < 4; nt++) {
                    mma16816(acc[mt][nt], ah + 4 * mt, bh + 2 * nt);
                    mma16816(acc[mt][nt], ah + 4 * mt, bl + 2 * nt);
                    mma16816(acc[mt][nt], al + 4 * mt, bh + 2 * nt);
                }
        }
        __syncthreads();
        if (c + 2 < NC) ISSUE(c + 2);
    }
#undef ISSUE

    int gid = lane >> 2, qid = lane & 3;
#pragma unroll
    for (int mt = 0; mt < 4; mt++) {
#pragma unroll
        for (int nt = 0; nt < 4; nt++) {
            int n = n0 + wn * 32 + nt * 8 + 2 * qid;
            float bsum0 = bias ? bias[n] : 0.f;
            float bsum1 = bias ? bias[n + 1] : 0.f;
#pragma unroll
            for (int half = 0; half < 2; half++) {
                int m = m0 + wm * 64 + mt * 16 + gid + half * 8;
                float v0 = acc[mt][nt][half * 2 + 0] + bsum0;
                float v1 = acc[mt][nt][half * 2 + 1] + bsum1;
                if (gelu) {
                    v0 = 0.5f * v0 * (1.f + erff(v0 * 0.70710678118654752f));
                    v1 = 0.5f * v1 * (1.f + erff(v1 * 0.70710678118654752f));
                }
                if (res) {
                    const float* rr = res + (size_t)m * N + n;
                    v0 += rr[0];
                    v1 += rr[1];
                }
                if (Cf) {
                    float2 o;
                    o.x = v0; o.y = v1;
                    *(float2*)(Cf + (size_t)m * N + n) = o;
                }
                if (Ch) {
                    __nv_bfloat162 oh, ol;
                    oh.x = __float2bfloat16(v0);
                    oh.y = __float2bfloat16(v1);
                    ol.x = __float2bfloat16(v0 - __bfloat162float(oh.x));
                    ol.y = __float2bfloat16(v1 - __bfloat162float(oh.y));
                    *(__nv_bfloat162*)(Ch + (size_t)m * N + n) = oh;
                    *(__nv_bfloat162*)(Cl + (size_t)m * N + n) = ol;
                }
            }
        }
    }
}

// ---------------------------------------------------------------------------
// MMA flash attention. CTA = 64 queries of one (b,h); 4 warps x 16 rows.
// Key tiles of 64; QK^T and P.V via m16n8k16 bf16, hi/lo 3-pass each.
// Online softmax in fp32 fragments. Causal mask on the diagonal tile only.
// ---------------------------------------------------------------------------
#define APITCH  144              // 64 bf16 = 128B data + 16B pad (ldsm conflict-free)
#define AT_TILE 9216             // 64 rows * APITCH
#define AT_Q    0                // Qh, Ql
#define AT_KV0  (2 * AT_TILE)    // per buffer: Kh, Kl, Vh, Vl
#define AT_KVS  (4 * AT_TILE)
#define AT_SMEM (AT_KV0 + 2 * AT_KVS)   // 92160

__global__ __launch_bounds__(128)
void attn_mma(const __nv_bfloat16* __restrict__ qkvh,
              const __nv_bfloat16* __restrict__ qkvl,
              __nv_bfloat16* __restrict__ oh,
              __nv_bfloat16* __restrict__ ol) {
    extern __shared__ __align__(128) char smem[];
    uint32_t sb = smem_u32(smem);
    int tid = threadIdx.x, w = tid >> 5, lane = tid & 31;
    int qi = (int)gridDim.x - 1 - (int)blockIdx.x;     // heavy tiles first
    int bh = blockIdx.y;
    int b = bh >> 4, h = bh & 15;
    const int RS = 3 * Cz;
    const size_t tokbase = (size_t)(b * Tz) * RS + h * Dz;

    int gid = lane >> 2, qid = lane & 3;
    int r16 = lane & 15, hsel = lane >> 4;
    int bg = lane >> 3;
    int browoff = ((bg & 2) << 2) + (lane & 7);
    int bkoff = (bg & 1) * 8;
    // trans-ldsm lane addressing for V
    int t_row = (bg & 1) * 8 + (lane & 7);   // key offset within 16
    int t_col = (bg >> 1) * 8;               // d offset within 16

    // ---- issue Q (group with KV tile 0), then KV tile 1 ----
#define ISSUE_KV(kt)                                                           \
    {                                                                          \
        uint32_t s0 = sb + AT_KV0 + ((kt) & 1) * AT_KVS;                       \
        const __nv_bfloat16* srcs[4] = {                                       \
            qkvh + tokbase + Cz, qkvl + tokbase + Cz,                          \
            qkvh + tokbase + 2 * Cz, qkvl + tokbase + 2 * Cz };                \
        _Pragma("unroll")                                                      \
        for (int t = 0; t < 4; t++) {                                          \
            _Pragma("unroll")                                                  \
            for (int it = 0; it < 4; it++) {                                   \
                int i = it * 128 + tid;                                        \
                int r = i >> 3, s = i & 7;                                     \
                cp16(s0 + t * AT_TILE + r * APITCH + s * 16,                   \
                     srcs[t] + (size_t)((kt) * 64 + r) * RS + s * 8);          \
            }                                                                  \
        }                                                                      \
        CP_COMMIT();                                                           \
    }

    {
        // Q tiles (hi, lo) + KV tile 0 in one group
#pragma unroll
        for (int t = 0; t < 2; t++) {
            const __nv_bfloat16* src = (t ? qkvl : qkvh) + tokbase;
            uint32_t dst = sb + AT_Q + t * AT_TILE;
#pragma unroll
            for (int it = 0; it < 4; it++) {
                int i = it * 128 + tid;
                int r = i >> 3, s = i & 7;
                cp16(dst + r * APITCH + s * 16,
                     src + (size_t)(qi * 64 + r) * RS + s * 8);
            }
        }
        uint32_t s0 = sb + AT_KV0;
        const __nv_bfloat16* srcs[4] = {
            qkvh + tokbase + Cz, qkvl + tokbase + Cz,
            qkvh + tokbase + 2 * Cz, qkvl + tokbase + 2 * Cz };
#pragma unroll
        for (int t = 0; t < 4; t++) {
#pragma unroll
            for (int it = 0; it < 4; it++) {
                int i = it * 128 + tid;
                int r = i >> 3, s = i & 7;
                cp16(s0 + t * AT_TILE + r * APITCH + s * 16,
                     srcs[t] + (size_t)r * RS + s * 8);
            }
        }
        CP_COMMIT();
    }
    if (qi >= 1) ISSUE_KV(1);

    if (qi >= 1) { CP_WAIT1(); } else { CP_WAIT0(); }
    __syncthreads();

    // ---- Q fragments (rows w*16..w*16+15, all 64 d) ----
    uint32_t qfh[4][4], qfl[4][4];
#pragma unroll
    for (int kk = 0; kk < 4; kk++) {
        uint32_t ad = sb + AT_Q + (uint32_t)((w * 16 + r16) * APITCH +
                                             (kk * 16 + hsel * 8) * 2);
        ldsm_x4(qfh[kk], ad);
        ldsm_x4(qfl[kk], ad + AT_TILE);
    }

    float oacc[8][4];
#pragma unroll
    for (int i = 0; i < 8; i++)
#pragma unroll
        for (int j = 0; j < 4; j++) oacc[i][j] = 0.f;
    float mrow[2] = {-1e30f, -1e30f};
    float lrow[2] = {0.f, 0.f};

    for (int kt = 0; kt <= qi; kt++) {
        if (kt > 0) {
            if (kt < qi) { CP_WAIT1(); } else { CP_WAIT0(); }
            __syncthreads();
        }
        uint32_t kb = sb + AT_KV0 + (kt & 1) * AT_KVS;

        // ---- scores S = Q K^T (3-pass) ----
        float s[8][4];
#pragma unroll
        for (int i = 0; i < 8; i++)
#pragma unroll
            for (int j = 0; j < 4; j++) s[i][j] = 0.f;
#pragma unroll
        for (int kk = 0; kk < 4; kk++) {
            uint32_t kh[16], kl[16];
#pragma unroll
            for (int np = 0; np < 4; np++) {
                uint32_t ad = kb + (uint32_t)((np * 16 + browoff) * APITCH +
                                              (kk * 16 + bkoff) * 2);
                ldsm_x4(kh + 4 * np, ad);
                ldsm_x4(kl + 4 * np, ad + AT_TILE);
            }
#pragma unroll
            for (int nt = 0; nt < 8; nt++) {
                uint32_t* bp = kh + (nt >> 1) * 4 + (nt & 1) * 2;
                uint32_t* bl2 = kl + (nt >> 1) * 4 + (nt & 1) * 2;
                mma16816(s[nt], qfh[kk], bp);
                mma16816(s[nt], qfh[kk], bl2);
                mma16816(s[nt], qfl[kk], bp);
            }
        }
        // scale + causal mask (diagonal tile only)
#pragma unroll
        for (int nt = 0; nt < 8; nt++)
#pragma unroll
            for (int j = 0; j < 4; j++) s[nt][j] *= 0.125f;
        if (kt == qi) {
#pragma unroll
            for (int nt = 0; nt < 8; nt++)
#pragma unroll
                for (int j = 0; j < 4; j++) {
                    int kc = 8 * nt + 2 * qid + (j & 1);
                    int qr = w * 16 + gid + (j >> 1) * 8;
                    if (kc > qr) s[nt][j] = -1e30f;
                }
        }
        // ---- online softmax ----
        float mt0 = -1e30f, mt1 = -1e30f;
#pragma unroll
        for (int nt = 0; nt < 8; nt++) {
            mt0 = fmaxf(mt0, fmaxf(s[nt][0], s[nt][1]));
            mt1 = fmaxf(mt1, fmaxf(s[nt][2], s[nt][3]));
        }
        mt0 = fmaxf(mt0, __shfl_xor_sync(0xffffffffu, mt0, 1));
        mt0 = fmaxf(mt0, __shfl_xor_sync(0xffffffffu, mt0, 2));
        mt1 = fmaxf(mt1, __shfl_xor_sync(0xffffffffu, mt1, 1));
        mt1 = fmaxf(mt1, __shfl_xor_sync(0xffffffffu, mt1, 2));
        float mn0 = fmaxf(mrow[0], mt0), mn1 = fmaxf(mrow[1], mt1);
        float c0 = __expf(mrow[0] - mn0), c1 = __expf(mrow[1] - mn1);
        mrow[0] = mn0; mrow[1] = mn1;
        float rs0 = 0.f, rs1 = 0.f;
#pragma unroll
        for (int nt = 0; nt < 8; nt++) {
            s[nt][0] = __expf(s[nt][0] - mn0);
            s[nt][1] = __expf(s[nt][1] - mn0);
            s[nt][2] = __expf(s[nt][2] - mn1);
            s[nt][3] = __expf(s[nt][3] - mn1);
            rs0 += s[nt][0] + s[nt][1];
            rs1 += s[nt][2] + s[nt][3];
        }
        rs0 += __shfl_xor_sync(0xffffffffu, rs0, 1);
        rs0 += __shfl_xor_sync(0xffffffffu, rs0, 2);
        rs1 += __shfl_xor_sync(0xffffffffu, rs1, 1);
        rs1 += __shfl_xor_sync(0xffffffffu, rs1, 2);
        lrow[0] = lrow[0] * c0 + rs0;
        lrow[1] = lrow[1] * c1 + rs1;
#pragma unroll
        for (int nt = 0; nt < 8; nt++) {
            oacc[nt][0] *= c0; oacc[nt][1] *= c0;
            oacc[nt][2] *= c1; oacc[nt][3] *= c1;
        }
        // ---- O += P V (3-pass) ----
#pragma unroll
        for (int k2 = 0; k2 < 4; k2++) {
            uint32_t pah[4], pal[4];
            {
                float p00 = s[2 * k2][0],     p01 = s[2 * k2][1];
                float p10 = s[2 * k2][2],     p11 = s[2 * k2][3];
                float p20 = s[2 * k2 + 1][0], p21 = s[2 * k2 + 1][1];
                float p30 = s[2 * k2 + 1][2], p31 = s[2 * k2 + 1][3];
                pah[0] = packbf(p00, p01);
                pah[1] = packbf(p10, p11);
                pah[2] = packbf(p20, p21);
                pah[3] = packbf(p30, p31);
                __nv_bfloat162* hp;
                hp = (__nv_bfloat162*)&pah[0];
                pal[0] = packbf(p00 - __bfloat162float(hp->x), p01 - __bfloat162float(hp->y));
                hp = (__nv_bfloat162*)&pah[1];
                pal[1] = packbf(p10 - __bfloat162float(hp->x), p11 - __bfloat162float(hp->y));
                hp = (__nv_bfloat162*)&pah[2];
                pal[2] = packbf(p20 - __bfloat162float(hp->x), p21 - __bfloat162float(hp->y));
                hp = (__nv_bfloat162*)&pah[3];
                pal[3] = packbf(p30 - __bfloat162float(hp->x), p31 - __bfloat162float(hp->y));
            }
            uint32_t vh[16], vl[16];
#pragma unroll
            for (int np = 0; np < 4; np++) {
                uint32_t ad = kb + 2 * AT_TILE +
                              (uint32_t)((k2 * 16 + t_row) * APITCH +
                                         (np * 16 + t_col) * 2);
                ldsm_x4t(vh + 4 * np, ad);
                ldsm_x4t(vl + 4 * np, ad + AT_TILE);
            }
#pragma unroll
            for (int nt = 0; nt < 8; nt++) {
                uint32_t* bp = vh + (nt >> 1) * 4 + (nt & 1) * 2;
                uint32_t* bl2 = vl + (nt >> 1) * 4 + (nt & 1) * 2;
                mma16816(oacc[nt], pah, bp);
                mma16816(oacc[nt], pah, bl2);
                mma16816(oacc[nt], pal, bp);
            }
        }
        __syncthreads();
        if (kt + 2 <= qi) ISSUE_KV(kt + 2);
    }
#undef ISSUE_KV

    // ---- epilogue ----
    float inv0 = 1.f / lrow[0], inv1 = 1.f / lrow[1];
    int tok0 = b * Tz + qi * 64 + w * 16 + gid;
#pragma unroll
    for (int nt = 0; nt < 8; nt++) {
        int col = h * Dz + 8 * nt + 2 * qid;
        float v0 = oacc[nt][0] * inv0, v1 = oacc[nt][1] * inv0;
        float v2 = oacc[nt][2] * inv1, v3 = oacc[nt][3] * inv1;
        __nv_bfloat162 ph, pl;
        ph.x = __float2bfloat16(v0); ph.y = __float2bfloat16(v1);
        pl.x = __float2bfloat16(v0 - __bfloat162float(ph.x));
        pl.y = __float2bfloat16(v1 - __bfloat162float(ph.y));
        *(__nv_bfloat162*)(oh + (size_t)tok0 * Cz + col) = ph;
        *(__nv_bfloat162*)(ol + (size_t)tok0 * Cz + col) = pl;
        ph.x = __float2bfloat16(v2); ph.y = __float2bfloat16(v3);
        pl.x = __float2bfloat16(v2 - __bfloat162float(ph.x));
        pl.y = __float2bfloat16(v3 - __bfloat162float(ph.y));
        *(__nv_bfloat162*)(oh + (size_t)(tok0 + 8) * Cz + col) = ph;
        *(__nv_bfloat162*)(ol + (size_t)(tok0 + 8) * Cz + col) = pl;
    }
}

// ---------------------------------------------------------------------------
// Embedding
// ---------------------------------------------------------------------------
__global__ void embed_kernel(const int* __restrict__ idx,
                             const float* __restrict__ tok,
                             const float* __restrict__ pos,
                             float* __restrict__ x) {
    int row = blockIdx.x;
    int t   = row & (Tz - 1);
    int tokid = idx[row];
    const float* te = tok + (size_t)tokid * Cz;
    const float* pe = pos + (size_t)t * Cz;
    float* xr = x + (size_t)row * Cz;
    for (int i = threadIdx.x; i < Cz; i += blockDim.x)
        xr[i] = te[i] + pe[i];
}

// ---------------------------------------------------------------------------
// LayerNorm per row, writes bf16 hi/lo split
// ---------------------------------------------------------------------------
__global__ void ln_kernel(const float* __restrict__ x,
                          __nv_bfloat16* __restrict__ yh,
                          __nv_bfloat16* __restrict__ yl,
                          const float* __restrict__ g, const float* __restrict__ b) {
    int row = blockIdx.x;
    const float* xr = x + (size_t)row * Cz;
    float s = 0.f, s2 = 0.f;
    for (int i = threadIdx.x; i < Cz; i += blockDim.x) {
        float v = xr[i];
        s += v; s2 += v * v;
    }
    __shared__ float sh_s[8], sh_s2[8];
    for (int off = 16; off > 0; off >>= 1) {
        s  += __shfl_down_sync(0xffffffffu, s,  off);
        s2 += __shfl_down_sync(0xffffffffu, s2, off);
    }
    int lane = threadIdx.x & 31, wid = threadIdx.x >> 5;
    if (lane == 0) { sh_s[wid] = s; sh_s2[wid] = s2; }
    __syncthreads();
    if (wid == 0) {
        s  = (lane < 8) ? sh_s[lane]  : 0.f;
        s2 = (lane < 8) ? sh_s2[lane] : 0.f;
        for (int off = 4; off > 0; off >>= 1) {
            s  += __shfl_down_sync(0xffffffffu, s,  off);
            s2 += __shfl_down_sync(0xffffffffu, s2, off);
        }
        if (lane == 0) { sh_s[0] = s; sh_s2[0] = s2; }
    }
    __syncthreads();
    float mean = sh_s[0] * (1.f / Cz);
    float var  = sh_s2[0] * (1.f / Cz) - mean * mean;
    float rstd = rsqrtf(var + EPSz);
    __nv_bfloat16* yhr = yh + (size_t)row * Cz;
    __nv_bfloat16* ylr = yl + (size_t)row * Cz;
    for (int i = threadIdx.x; i < Cz; i += blockDim.x) {
        float v = (xr[i] - mean) * rstd * g[i] + b[i];
        __nv_bfloat16 h = __float2bfloat16(v);
        yhr[i] = h;
        ylr[i] = __float2bfloat16(v - __bfloat162float(h));
    }
}

// ---------------------------------------------------------------------------
// Launch
// ---------------------------------------------------------------------------
extern "C" void kernel_launch(void* const* d_in, const int* in_sizes, int n_in,
                              void* d_out, int out_size) {
    const int*   idx     = (const int*)  d_in[0];
    const float* tok_emb = (const float*)d_in[1];
    const float* pos_emb = (const float*)d_in[2];
    const float* qkv_w   = (const float*)d_in[3];
    const float* proj_w  = (const float*)d_in[4];
    const float* proj_b  = (const float*)d_in[5];
    const float* ln1_g   = (const float*)d_in[6];
    const float* ln1_b   = (const float*)d_in[7];
    const float* ln2_g   = (const float*)d_in[8];
    const float* ln2_b   = (const float*)d_in[9];
    const float* fc1_w   = (const float*)d_in[10];
    const float* fc1_b   = (const float*)d_in[11];
    const float* fc2_w   = (const float*)d_in[12];
    const float* fc2_b   = (const float*)d_in[13];
    const float* lnf_g   = (const float*)d_in[14];
    const float* lnf_b   = (const float*)d_in[15];
    float* out = (float*)d_out;

    float* x;
    cudaGetSymbolAddress((void**)&x, g_x);
    __nv_bfloat16 *hh, *hl, *qkvh, *qkvl, *atth, *attl, *ffnh, *ffnl;
    cudaGetSymbolAddress((void**)&hh,   g_hh);
    cudaGetSymbolAddress((void**)&hl,   g_hl);
    cudaGetSymbolAddress((void**)&qkvh, g_qkvh);
    cudaGetSymbolAddress((void**)&qkvl, g_qkvl);
    cudaGetSymbolAddress((void**)&atth, g_atth);
    cudaGetSymbolAddress((void**)&attl, g_attl);
    cudaGetSymbolAddress((void**)&ffnh, g_ffnh);
    cudaGetSymbolAddress((void**)&ffnl, g_ffnl);
    __nv_bfloat16 *qkvTh, *qkvTl, *projTh, *projTl, *fc1Th, *fc1Tl, *fc2Th, *fc2Tl, *tokh, *tokl;
    cudaGetSymbolAddress((void**)&qkvTh, g_qkvT_hi);
    cudaGetSymbolAddress((void**)&qkvTl, g_qkvT_lo);
    cudaGetSymbolAddress((void**)&projTh, g_projT_hi);
    cudaGetSymbolAddress((void**)&projTl, g_projT_lo);
    cudaGetSymbolAddress((void**)&fc1Th, g_fc1T_hi);
    cudaGetSymbolAddress((void**)&fc1Tl, g_fc1T_lo);
    cudaGetSymbolAddress((void**)&fc2Th, g_fc2T_hi);
    cudaGetSymbolAddress((void**)&fc2Tl, g_fc2T_lo);
    cudaGetSymbolAddress((void**)&tokh, g_tok_hi);
    cudaGetSymbolAddress((void**)&tokl, g_tok_lo);

    cudaFuncSetAttribute(gemm_mma, cudaFuncAttributeMaxDynamicSharedMemorySize, GSMEM);
    cudaFuncSetAttribute(attn_mma, cudaFuncAttributeMaxDynamicSharedMemorySize, AT_SMEM);

    // ---- weight prep ----
    dim3 tb(32, 8);
    wtrans_kernel<<<dim3(3 * Cz / 32, Cz / 32, Lz), tb>>>(qkv_w, qkvTh, qkvTl, Cz, 3 * Cz);
    wtrans_kernel<<<dim3(Cz / 32, Cz / 32, Lz), tb>>>(proj_w, projTh, projTl, Cz, Cz);
    wtrans_kernel<<<dim3(HIDz / 32, Cz / 32, Lz), tb>>>(fc1_w, fc1Th, fc1Tl, Cz, HIDz);
    wtrans_kernel<<<dim3(Cz / 32, HIDz / 32, Lz), tb>>>(fc2_w, fc2Th, fc2Tl, HIDz, Cz);
    wsplit_kernel<<<(Vz * Cz + 255) / 256, 256>>>(tok_emb, tokh, tokl, Vz * Cz);

    embed_kernel<<<NTOK, 256>>>(idx, tok_emb, pos_emb, x);

    for (int l = 0; l < Lz; l++) {
        const __nv_bfloat16* qwh = qkvTh + (size_t)l * 3 * Cz * Cz;
        const __nv_bfloat16* qwl = qkvTl + (size_t)l * 3 * Cz * Cz;
        const __nv_bfloat16* pwh = projTh + (size_t)l * Cz * Cz;
        const __nv_bfloat16* pwl = projTl + (size_t)l * Cz * Cz;
        const __nv_bfloat16* w1h = fc1Th + (size_t)l * Cz * HIDz;
        const __nv_bfloat16* w1l = fc1Tl + (size_t)l * Cz * HIDz;
        const __nv_bfloat16* w2h = fc2Th + (size_t)l * Cz * HIDz;
        const __nv_bfloat16* w2l = fc2Tl + (size_t)l * Cz * HIDz;
        const float* pb  = proj_b + (size_t)l * Cz;
        const float* b1  = fc1_b  + (size_t)l * HIDz;
        const float* b2  = fc2_b  + (size_t)l * Cz;

        ln_kernel<<<NTOK, 256>>>(x, hh, hl, ln1_g + l * Cz, ln1_b + l * Cz);
        gemm_mma<<<dim3(3 * Cz / 128, NTOK / 128), 256, GSMEM>>>(
            hh, hl, qwh, qwl, nullptr, qkvh, qkvl,
            NTOK, 3 * Cz, Cz, nullptr, nullptr, 0);
        attn_mma<<<dim3(Tz / 64, Bz * Hz), 128, AT_SMEM>>>(qkvh, qkvl, atth, attl);
        gemm_mma<<<dim3(Cz / 128, NTOK / 128), 256, GSMEM>>>(
            atth, attl, pwh, pwl, x, nullptr, nullptr,
            NTOK, Cz, Cz, pb, x, 0);
        ln_kernel<<<NTOK, 256>>>(x, hh, hl, ln2_g + l * Cz, ln2_b + l * Cz);
        gemm_mma<<<dim3(HIDz / 128, NTOK / 128), 256, GSMEM>>>(
            hh, hl, w1h, w1l, nullptr, ffnh, ffnl,
            NTOK, HIDz, Cz, b1, nullptr, 1);
        gemm_mma<<<dim3(Cz / 128, NTOK / 128), 256, GSMEM>>>(
            ffnh, ffnl, w2h, w2l, x, nullptr, nullptr,
            NTOK, Cz, HIDz, b2, x, 0);
    }

    ln_kernel<<<NTOK, 256>>>(x, hh, hl, lnf_g, lnf_b);
    gemm_mma<<<dim3(Vz / 128, NTOK / 128), 256, GSMEM>>>(
        hh, hl, tokh, tokl, out, nullptr, nullptr,
        NTOK, Vz, Cz, nullptr, nullptr, 0);
}